// round 2
// baseline (speedup 1.0000x reference)
#include <cuda_runtime.h>
#include <cuda_bf16.h>
#include <cstdint>

// Problem constants
#define BB 16
#define SS 4096
#define EE 1024
#define HH 512

// Scratch (device globals — no allocation allowed)
__device__ float g_db[BB * HH];      // combined dec_proj + bd + be
__device__ float g_scores[BB * SS];
__device__ float g_attn[BB * SS];

// ---------------- helpers ----------------
__device__ __forceinline__ uint32_t f2tf(float x) {
    uint32_t u;
    asm("cvt.rna.tf32.f32 %0, %1;" : "=r"(u) : "f"(x));
    return u;
}

__device__ __forceinline__ void mma_tf32(float c[4],
                                         uint32_t a0, uint32_t a1, uint32_t a2, uint32_t a3,
                                         uint32_t b0, uint32_t b1) {
    asm volatile(
        "mma.sync.aligned.m16n8k8.row.col.f32.tf32.tf32.f32 "
        "{%0,%1,%2,%3}, {%4,%5,%6,%7}, {%8,%9}, {%0,%1,%2,%3};\n"
        : "+f"(c[0]), "+f"(c[1]), "+f"(c[2]), "+f"(c[3])
        : "r"(a0), "r"(a1), "r"(a2), "r"(a3), "r"(b0), "r"(b1));
}

__device__ __forceinline__ void cp16(float* dst_smem, const float* src) {
    uint32_t d = (uint32_t)__cvta_generic_to_shared(dst_smem);
    asm volatile("cp.async.cg.shared.global [%0], [%1], 16;\n" :: "r"(d), "l"(src));
}

__device__ __forceinline__ float tanh_acc(float x) {
    float xa = fminf(fmaxf(x, -12.f), 12.f);
    float e = __expf(2.f * xa);
    return (e - 1.f) / (e + 1.f);
}

// ---------------- K1: decoder projection + biases ----------------
__global__ void k1_decproj(const float* __restrict__ dec, const float* __restrict__ Wd,
                           const float* __restrict__ bd, const float* __restrict__ be) {
    int b = blockIdx.x;          // 16 blocks
    int h = threadIdx.x;         // 512 threads
    const float* d = dec + b * EE;
    float s0 = 0.f, s1 = 0.f, s2 = 0.f, s3 = 0.f;
    for (int e = 0; e < EE; e += 4) {
        s0 += d[e + 0] * Wd[(e + 0) * HH + h];
        s1 += d[e + 1] * Wd[(e + 1) * HH + h];
        s2 += d[e + 2] * Wd[(e + 2) * HH + h];
        s3 += d[e + 3] * Wd[(e + 3) * HH + h];
    }
    g_db[b * HH + h] = (s0 + s1) + (s2 + s3) + bd[h] + be[h];
}

// ---------------- K2: fused enc@We + tanh + Wo-dot -> scores ----------------
// Block: 256 threads (8 warps). Tile: 64 s-rows x 512 h-cols, K streamed in 32-chunks.
// Warp w owns h-columns [w*64, w*64+64). Accum: 4 m-tiles x 8 n-tiles x 4 regs.
#define KC 32
#define APITCH 36     // 64 x 36 floats per A buffer (padded: conflict-free frag loads)
#define BPITCH 520    // 32 x 520 floats per B buffer (pad 8: conflict-free frag loads)
#define ABUF (64 * APITCH)
#define BBUF (32 * BPITCH)

__global__ __launch_bounds__(256, 1)
void k2_scores(const float* __restrict__ enc, const float* __restrict__ We,
               const float* __restrict__ Wo, const float* __restrict__ bo) {
    extern __shared__ float sm[];
    float* As   = sm;                       // 2 * ABUF
    float* Bs   = sm + 2 * ABUF;            // 2 * BBUF
    float* db_s = Bs + 2 * BBUF;            // 512
    float* wo_s = db_s + HH;                // 512
    float* red  = wo_s + HH;                // 8 * 64

    const int tid = threadIdx.x;
    const int b   = blockIdx.y;
    const int s0  = blockIdx.x * 64;
    const float* A = enc + (size_t)(b * SS + s0) * EE;

    // preload db and Wo
    db_s[tid]       = g_db[b * HH + tid];
    db_s[tid + 256] = g_db[b * HH + tid + 256];
    wo_s[tid]       = Wo[tid];
    wo_s[tid + 256] = Wo[tid + 256];

    auto loadA = [&](int kc, int buf) {
#pragma unroll
        for (int j = 0; j < 2; j++) {
            int i = tid + j * 256;         // 512 float4 total
            int r = i >> 3, c4 = i & 7;
            cp16(As + buf * ABUF + r * APITCH + c4 * 4,
                 A + (size_t)r * EE + kc * KC + c4 * 4);
        }
    };
    auto loadB = [&](int kc, int buf) {
#pragma unroll
        for (int j = 0; j < 16; j++) {
            int i = tid + j * 256;         // 4096 float4 total
            int r = i >> 7, c4 = i & 127;
            cp16(Bs + buf * BBUF + r * BPITCH + c4 * 4,
                 We + (size_t)(kc * KC + r) * HH + c4 * 4);
        }
    };

    loadA(0, 0); loadB(0, 0);
    asm volatile("cp.async.commit_group;\n");
    loadA(1, 1); loadB(1, 1);
    asm volatile("cp.async.commit_group;\n");

    float acc[4][8][4] = {};
    const int w = tid >> 5, lane = tid & 31;
    const int g = lane >> 2, t4 = lane & 3;

    for (int kc = 0; kc < EE / KC; kc++) {
        asm volatile("cp.async.wait_group 1;\n");
        __syncthreads();
        const float* Ab = As + (kc & 1) * ABUF;
        const float* Bb = Bs + (kc & 1) * BBUF;
#pragma unroll
        for (int ks = 0; ks < 4; ks++) {
            const int k = ks * 8;
            uint32_t a[4][4];
#pragma unroll
            for (int mt = 0; mt < 4; mt++) {
                int r = mt * 16 + g;
                a[mt][0] = f2tf(Ab[r * APITCH + k + t4]);
                a[mt][1] = f2tf(Ab[(r + 8) * APITCH + k + t4]);
                a[mt][2] = f2tf(Ab[r * APITCH + k + t4 + 4]);
                a[mt][3] = f2tf(Ab[(r + 8) * APITCH + k + t4 + 4]);
            }
#pragma unroll
            for (int nt = 0; nt < 8; nt++) {
                int n = w * 64 + nt * 8 + g;
                uint32_t b0 = f2tf(Bb[(k + t4) * BPITCH + n]);
                uint32_t b1 = f2tf(Bb[(k + t4 + 4) * BPITCH + n]);
#pragma unroll
                for (int mt = 0; mt < 4; mt++)
                    mma_tf32(acc[mt][nt], a[mt][0], a[mt][1], a[mt][2], a[mt][3], b0, b1);
            }
        }
        __syncthreads();
        if (kc + 2 < EE / KC) { loadA(kc + 2, kc & 1); loadB(kc + 2, kc & 1); }
        asm volatile("cp.async.commit_group;\n");
    }

    // Epilogue: tanh(acc + db) * Wo, reduce over h
    float psum[8] = {};
#pragma unroll
    for (int mt = 0; mt < 4; mt++) {
#pragma unroll
        for (int nt = 0; nt < 8; nt++) {
            int h0 = w * 64 + nt * 8 + t4 * 2;
            float d0 = db_s[h0], d1 = db_s[h0 + 1];
            float w0 = wo_s[h0], w1 = wo_s[h0 + 1];
            psum[mt * 2]     += tanh_acc(acc[mt][nt][0] + d0) * w0
                              + tanh_acc(acc[mt][nt][1] + d1) * w1;
            psum[mt * 2 + 1] += tanh_acc(acc[mt][nt][2] + d0) * w0
                              + tanh_acc(acc[mt][nt][3] + d1) * w1;
        }
    }
#pragma unroll
    for (int i = 0; i < 8; i++) {
        psum[i] += __shfl_xor_sync(0xffffffffu, psum[i], 1);
        psum[i] += __shfl_xor_sync(0xffffffffu, psum[i], 2);
    }
    if (t4 == 0) {
#pragma unroll
        for (int mt = 0; mt < 4; mt++) {
            red[w * 64 + mt * 16 + g]     = psum[mt * 2];
            red[w * 64 + mt * 16 + 8 + g] = psum[mt * 2 + 1];
        }
    }
    __syncthreads();
    if (tid < 64) {
        float sc = bo[0];
#pragma unroll
        for (int ww = 0; ww < 8; ww++) sc += red[ww * 64 + tid];
        g_scores[b * SS + s0 + tid] = sc;
    }
}

// ---------------- K3: softmax over S per batch ----------------
__global__ void k3_softmax() {
    int b = blockIdx.x, tid = threadIdx.x;      // 256 threads
    __shared__ float sred[256];
    const float* sc = g_scores + b * SS;
    float mx = -1e30f;
    for (int i = tid; i < SS; i += 256) mx = fmaxf(mx, sc[i]);
    sred[tid] = mx; __syncthreads();
    for (int st = 128; st > 0; st >>= 1) {
        if (tid < st) sred[tid] = fmaxf(sred[tid], sred[tid + st]);
        __syncthreads();
    }
    mx = sred[0]; __syncthreads();
    float sum = 0.f;
    for (int i = tid; i < SS; i += 256) {
        float e = __expf(sc[i] - mx);
        g_attn[b * SS + i] = e;
        sum += e;
    }
    sred[tid] = sum; __syncthreads();
    for (int st = 128; st > 0; st >>= 1) {
        if (tid < st) sred[tid] += sred[tid + st];
        __syncthreads();
    }
    float inv = 1.f / sred[0];
    for (int i = tid; i < SS; i += 256) g_attn[b * SS + i] *= inv;
}

// ---------------- K4: context = attn . enc ----------------
__global__ __launch_bounds__(128)
void k4_context(const float* __restrict__ enc, float* __restrict__ out) {
    int b  = blockIdx.z;
    int e  = blockIdx.x * 128 + threadIdx.x;
    int s0 = blockIdx.y * (SS / 8);   // 512 rows per block
    __shared__ float at[SS / 8];
    for (int i = threadIdx.x; i < SS / 8; i += 128) at[i] = g_attn[b * SS + s0 + i];
    __syncthreads();
    const float* ep = enc + (size_t)(b * SS + s0) * EE + e;
    float a0 = 0.f, a1 = 0.f, a2 = 0.f, a3 = 0.f;
#pragma unroll 4
    for (int s = 0; s < SS / 8; s += 4) {
        a0 += at[s + 0] * ep[(size_t)(s + 0) * EE];
        a1 += at[s + 1] * ep[(size_t)(s + 1) * EE];
        a2 += at[s + 2] * ep[(size_t)(s + 2) * EE];
        a3 += at[s + 3] * ep[(size_t)(s + 3) * EE];
    }
    atomicAdd(&out[b * EE + e], (a0 + a1) + (a2 + a3));
}

// ---------------- launch ----------------
extern "C" void kernel_launch(void* const* d_in, const int* in_sizes, int n_in,
                              void* d_out, int out_size) {
    const float* enc = (const float*)d_in[0];
    const float* dec = (const float*)d_in[1];
    const float* We  = (const float*)d_in[2];
    const float* be  = (const float*)d_in[3];
    const float* Wd  = (const float*)d_in[4];
    const float* bd  = (const float*)d_in[5];
    const float* Wo  = (const float*)d_in[6];
    const float* bo  = (const float*)d_in[7];
    float* out = (float*)d_out;

    k1_decproj<<<BB, HH>>>(dec, Wd, bd, be);

    size_t smem2 = (size_t)(2 * ABUF + 2 * BBUF + HH + HH + 8 * 64) * sizeof(float);
    cudaFuncSetAttribute(k2_scores, cudaFuncAttributeMaxDynamicSharedMemorySize, (int)smem2);
    k2_scores<<<dim3(SS / 64, BB), 256, smem2>>>(enc, We, Wo, bo);

    k3_softmax<<<BB, 256>>>();

    cudaMemsetAsync(d_out, 0, (size_t)BB * EE * sizeof(float));
    k4_context<<<dim3(EE / 128, 8, BB), 128>>>(enc, out);
}